// round 16
// baseline (speedup 1.0000x reference)
#include <cuda_runtime.h>
#include <cstdint>

// Problem shape (fixed for this problem instance)
#define B_  8
#define N_  256
#define T_  64
#define D_  512
#define NT_ (N_ * T_)          // 16384
#define ROWS_ (B_ * NT_)       // 131072
#define RPB_ 16                // rows per block (divides T_, so one segment/block)
#define BPB_ (NT_ / RPB_)      // blocks per batch = 1024

// ---------------------------------------------------------------------------
// Single fused kernel. One 256-thread block per 16 consecutive output rows
// (always within one segment since 16 | 64). RPB=16 measured best granularity
// (R14: kernel 61.9us, DRAM 72.4%). This round: occupancy 6 -> 8 blocks/SM
// via __launch_bounds__(256,8) (reg cap 32).
//   1. shfl-based scan of length[] (2 barriers)
//   2. binary-search 16 src row indices into smem
//   3. specialized paths: fully-valid / fully-invalid / boundary
// ---------------------------------------------------------------------------
__global__ __launch_bounds__(256, 8) void write_all(
    const float* __restrict__ x,       // (B, NT, D)
    const float* __restrict__ x_gcn,   // (B, N, D)
    const int*   __restrict__ length,  // (B, N)
    const int*   __restrict__ tags,    // (B, NT) int32
    float* __restrict__ out_x,         // (B, NT, D)
    float* __restrict__ out_mask,      // (B, NT)
    float* __restrict__ out_tag,       // (B, NT)
    float* __restrict__ out_dsl,       // (B,)
    int do_tails)
{
    int bid  = blockIdx.x;             // [0, B*BPB_)
    int b    = bid >> 10;              // / BPB_ (1024)
    int jbase = (bid & (BPB_ - 1)) * RPB_;   // first output row (within batch)
    int nOut = jbase >> 6;             // segment index (jbase / T_)
    int tid  = threadIdx.x;
    int lane = tid & 127;              // float4 lane within a row
    int half = tid >> 7;               // 0/1: two rows interleaved
    int laneid = tid & 31;
    int wid    = tid >> 5;

    __shared__ int s_off[N_];          // exclusive offsets
    __shared__ int s_warp[8];
    __shared__ int s_src[RPB_];

    // --- shfl-based scan of this batch's 256 lengths (2 barriers) ---
    int v = length[b * N_ + tid];
    int sum = v;
    #pragma unroll
    for (int o = 1; o < 32; o <<= 1) {
        int t = __shfl_up_sync(0xffffffffu, sum, o);
        if (laneid >= o) sum += t;
    }
    if (laneid == 31) s_warp[wid] = sum;
    __syncthreads();
    if (wid == 0 && laneid < 8) {
        int w = s_warp[laneid];
        #pragma unroll
        for (int o = 1; o < 8; o <<= 1) {
            int t = __shfl_up_sync(0xffu, w, o);
            if (laneid >= o) w += t;
        }
        s_warp[laneid] = w;            // inclusive scan of warp totals
    }
    __syncthreads();
    int warpbase = (wid > 0) ? s_warp[wid - 1] : 0;
    int dsl = s_warp[7];               // doc_seq_len of this batch
    s_off[tid] = warpbase + sum - v;   // exclusive prefix
    __syncthreads();

    // --- 16 threads resolve src rows via binary search over offsets ---
    if (tid < RPB_) {
        int j = jbase + tid;
        if (j < dsl) {
            int lo = 0, hi = N_ - 1;
            #pragma unroll
            for (int it = 0; it < 8; it++) {       // log2(256)
                int mid = (lo + hi + 1) >> 1;
                if (s_off[mid] <= j) lo = mid; else hi = mid - 1;
            }
            s_src[tid] = lo * T_ + (j - s_off[lo]);
        }
    }

    // gcn row for this block's segment: loaded once, reused for all 16 rows
    const float4 g = reinterpret_cast<const float4*>(
        x_gcn + ((size_t)(b * N_ + nOut) * D_))[lane];
    __syncthreads();

    const float* xb  = x     + (size_t)b * NT_ * D_;
    float*       oxb = out_x + (size_t)b * NT_ * D_;

    if (jbase + RPB_ <= dsl) {
        // ================= fully valid: clean 4-deep stream =================
        #pragma unroll
        for (int c = 0; c < 2; c++) {
            int r0 = c * 8 + half;
            float4 vv[4];
            #pragma unroll
            for (int k = 0; k < 4; k++)
                vv[k] = reinterpret_cast<const float4*>(
                    xb + (size_t)s_src[r0 + 2 * k] * D_)[lane];
            #pragma unroll
            for (int k = 0; k < 4; k++) {
                int r = r0 + 2 * k;
                float4 o;
                o.x = g.x + vv[k].x; o.y = g.y + vv[k].y;
                o.z = g.z + vv[k].z; o.w = g.w + vv[k].w;
                reinterpret_cast<float4*>(oxb + (size_t)(jbase + r) * D_)[lane] = o;
                if (do_tails && lane == 0) {
                    int fi = b * NT_ + jbase + r;
                    out_mask[fi] = 1.0f;
                    out_tag[fi]  = (float)tags[b * NT_ + s_src[r]];
                }
            }
        }
    } else if (jbase >= dsl) {
        // ================= fully invalid: pure gcn write ====================
        #pragma unroll
        for (int r = half; r < RPB_; r += 2) {
            reinterpret_cast<float4*>(oxb + (size_t)(jbase + r) * D_)[lane] = g;
            if (do_tails && lane == 0) {
                int fi = b * NT_ + jbase + r;
                out_mask[fi] = 0.0f;
                out_tag[fi]  = 0.0f;
            }
        }
    } else {
        // ================= boundary (1 block per batch) =====================
        for (int r = half; r < RPB_; r += 2) {
            int j = jbase + r;
            bool valid = (j < dsl);
            float4 o = g;
            int src = valid ? s_src[r] : 0;
            if (valid) {
                float4 vv = reinterpret_cast<const float4*>(
                    xb + (size_t)src * D_)[lane];
                o.x += vv.x; o.y += vv.y; o.z += vv.z; o.w += vv.w;
            }
            reinterpret_cast<float4*>(oxb + (size_t)j * D_)[lane] = o;
            if (do_tails && lane == 0) {
                int fi = b * NT_ + j;
                out_mask[fi] = valid ? 1.0f : 0.0f;
                out_tag[fi]  = valid ? (float)tags[b * NT_ + src] : 0.0f;
            }
        }
    }

    // first block of EACH batch writes its own dsl
    if (do_tails && jbase == 0 && tid == 0)
        out_dsl[b] = (float)dsl;
}

// ---------------------------------------------------------------------------
extern "C" void kernel_launch(void* const* d_in, const int* in_sizes, int n_in,
                              void* d_out, int out_size) {
    const float* x      = (const float*)d_in[0];      // (B,N,T,D)
    const float* x_gcn  = (const float*)d_in[1];      // (B,N,D)
    // d_in[2] = mask (unused: prefix mask fully determined by length)
    const int*   length = (const int*)d_in[3];        // (B,N)
    const int*   tags   = (const int*)d_in[4];        // (B,N,T) int32 (JAX downcast)

    float* out = (float*)d_out;
    // Output layout: [new_x | new_mask | doc_seq_len | new_tag] flattened fp32
    const size_t nx_elems = (size_t)ROWS_ * D_;       // 67,108,864
    float* out_x    = out;
    float* out_mask = out + nx_elems;
    float* out_dsl  = out_mask + ROWS_;
    float* out_tag  = out_dsl + B_;

    int do_tails = ((size_t)out_size >= nx_elems + 2 * ROWS_ + B_) ? 1 : 0;

    write_all<<<B_ * BPB_, 256>>>(x, x_gcn, length, tags,
                                  out_x, out_mask, out_tag, out_dsl, do_tails);
}

// round 17
// speedup vs baseline: 1.0213x; 1.0213x over previous
#include <cuda_runtime.h>
#include <cstdint>

// Problem shape (fixed for this problem instance)
#define B_  8
#define N_  256
#define T_  64
#define D_  512
#define NT_ (N_ * T_)          // 16384
#define ROWS_ (B_ * NT_)       // 131072
#define RPB_ 16                // rows per block (divides T_, so one segment/block)
#define BPB_ (NT_ / RPB_)      // blocks per batch = 1024

// ---------------------------------------------------------------------------
// Single fused kernel. One 256-thread block per 16 consecutive output rows
// (always within one segment since 16 | 64). Best-measured config: RPB=16,
// occ=6 (R14: kernel 61.9us, DRAM 72.4%). This round: mask/tag tail stores
// hoisted out of the hot loop so the stream is pure LDG.128/STG.128.
// ---------------------------------------------------------------------------
__global__ __launch_bounds__(256, 6) void write_all(
    const float* __restrict__ x,       // (B, NT, D)
    const float* __restrict__ x_gcn,   // (B, N, D)
    const int*   __restrict__ length,  // (B, N)
    const int*   __restrict__ tags,    // (B, NT) int32
    float* __restrict__ out_x,         // (B, NT, D)
    float* __restrict__ out_mask,      // (B, NT)
    float* __restrict__ out_tag,       // (B, NT)
    float* __restrict__ out_dsl,       // (B,)
    int do_tails)
{
    int bid  = blockIdx.x;             // [0, B*BPB_)
    int b    = bid >> 10;              // / BPB_ (1024)
    int jbase = (bid & (BPB_ - 1)) * RPB_;   // first output row (within batch)
    int nOut = jbase >> 6;             // segment index (jbase / T_)
    int tid  = threadIdx.x;
    int lane = tid & 127;              // float4 lane within a row
    int half = tid >> 7;               // 0/1: two rows interleaved
    int laneid = tid & 31;
    int wid    = tid >> 5;

    __shared__ int s_off[N_];          // exclusive offsets
    __shared__ int s_warp[8];
    __shared__ int s_src[RPB_];

    // --- shfl-based scan of this batch's 256 lengths (2 barriers) ---
    int v = length[b * N_ + tid];
    int sum = v;
    #pragma unroll
    for (int o = 1; o < 32; o <<= 1) {
        int t = __shfl_up_sync(0xffffffffu, sum, o);
        if (laneid >= o) sum += t;
    }
    if (laneid == 31) s_warp[wid] = sum;
    __syncthreads();
    if (wid == 0 && laneid < 8) {
        int w = s_warp[laneid];
        #pragma unroll
        for (int o = 1; o < 8; o <<= 1) {
            int t = __shfl_up_sync(0xffu, w, o);
            if (laneid >= o) w += t;
        }
        s_warp[laneid] = w;            // inclusive scan of warp totals
    }
    __syncthreads();
    int warpbase = (wid > 0) ? s_warp[wid - 1] : 0;
    int dsl = s_warp[7];               // doc_seq_len of this batch
    s_off[tid] = warpbase + sum - v;   // exclusive prefix
    __syncthreads();

    // --- 16 threads: binary-search src rows AND write mask/tag tails here,
    //     keeping the main stream loop free of divergent scalar stores ---
    if (tid < RPB_) {
        int j = jbase + tid;
        bool valid = (j < dsl);
        int src = 0;
        if (valid) {
            int lo = 0, hi = N_ - 1;
            #pragma unroll
            for (int it = 0; it < 8; it++) {       // log2(256)
                int mid = (lo + hi + 1) >> 1;
                if (s_off[mid] <= j) lo = mid; else hi = mid - 1;
            }
            src = lo * T_ + (j - s_off[lo]);
            s_src[tid] = src;
        }
        if (do_tails) {
            int fi = b * NT_ + j;
            out_mask[fi] = valid ? 1.0f : 0.0f;
            out_tag[fi]  = valid ? (float)tags[b * NT_ + src] : 0.0f;
        }
    }

    // gcn row for this block's segment: loaded once, reused for all 16 rows
    const float4 g = reinterpret_cast<const float4*>(
        x_gcn + ((size_t)(b * N_ + nOut) * D_))[lane];
    __syncthreads();

    const float* xb  = x     + (size_t)b * NT_ * D_;
    float*       oxb = out_x + (size_t)b * NT_ * D_;

    if (jbase + RPB_ <= dsl) {
        // ================= fully valid: clean 4-deep stream =================
        #pragma unroll
        for (int c = 0; c < 2; c++) {
            int r0 = c * 8 + half;
            float4 vv[4];
            #pragma unroll
            for (int k = 0; k < 4; k++)
                vv[k] = reinterpret_cast<const float4*>(
                    xb + (size_t)s_src[r0 + 2 * k] * D_)[lane];
            #pragma unroll
            for (int k = 0; k < 4; k++) {
                int r = r0 + 2 * k;
                float4 o;
                o.x = g.x + vv[k].x; o.y = g.y + vv[k].y;
                o.z = g.z + vv[k].z; o.w = g.w + vv[k].w;
                reinterpret_cast<float4*>(oxb + (size_t)(jbase + r) * D_)[lane] = o;
            }
        }
    } else if (jbase >= dsl) {
        // ================= fully invalid: pure gcn write ====================
        #pragma unroll
        for (int r = half; r < RPB_; r += 2)
            reinterpret_cast<float4*>(oxb + (size_t)(jbase + r) * D_)[lane] = g;
    } else {
        // ================= boundary (1 block per batch) =====================
        for (int r = half; r < RPB_; r += 2) {
            int j = jbase + r;
            bool valid = (j < dsl);
            float4 o = g;
            if (valid) {
                float4 vv = reinterpret_cast<const float4*>(
                    xb + (size_t)s_src[r] * D_)[lane];
                o.x += vv.x; o.y += vv.y; o.z += vv.z; o.w += vv.w;
            }
            reinterpret_cast<float4*>(oxb + (size_t)j * D_)[lane] = o;
        }
    }

    // first block of EACH batch writes its own dsl
    if (do_tails && jbase == 0 && tid == 0)
        out_dsl[b] = (float)dsl;
}

// ---------------------------------------------------------------------------
extern "C" void kernel_launch(void* const* d_in, const int* in_sizes, int n_in,
                              void* d_out, int out_size) {
    const float* x      = (const float*)d_in[0];      // (B,N,T,D)
    const float* x_gcn  = (const float*)d_in[1];      // (B,N,D)
    // d_in[2] = mask (unused: prefix mask fully determined by length)
    const int*   length = (const int*)d_in[3];        // (B,N)
    const int*   tags   = (const int*)d_in[4];        // (B,N,T) int32 (JAX downcast)

    float* out = (float*)d_out;
    // Output layout: [new_x | new_mask | doc_seq_len | new_tag] flattened fp32
    const size_t nx_elems = (size_t)ROWS_ * D_;       // 67,108,864
    float* out_x    = out;
    float* out_mask = out + nx_elems;
    float* out_dsl  = out_mask + ROWS_;
    float* out_tag  = out_dsl + B_;

    int do_tails = ((size_t)out_size >= nx_elems + 2 * ROWS_ + B_) ? 1 : 0;

    write_all<<<B_ * BPB_, 256>>>(x, x_gcn, length, tags,
                                  out_x, out_mask, out_tag, out_dsl, do_tails);
}